// round 1
// baseline (speedup 1.0000x reference)
#include <cuda_runtime.h>
#include <cstdint>

// Problem constants
#define TT 131072
#define BB 6
#define II 32
#define HH 3
#define LL 8
#define G3 9              // 3*H gates
#define CHUNK 32
#define NCH (TT / CHUNK)                  // 4096 chunks
#define XG_CHUNK_FLOATS (CHUNK * BB * G3) // 1728 floats per chunk
#define PREG_N (XG_CHUNK_FLOATS / 32)     // 54 per lane

// Scratch for layer-0 input projections: (T, B, 9) — __device__ global (allowed)
__device__ float g_xg0[(size_t)TT * BB * G3];

__device__ __forceinline__ float sigf(float x) {
    // 1/(1+e^-x); expf->inf for very negative x gives 1/inf = 0, no NaN.
    return __fdividef(1.0f, 1.0f + __expf(-x));
}
__device__ __forceinline__ float tanhf_fast(float x) {
    // (1-e)/(1+e), e = e^{-2x}; clamp to avoid inf/inf NaN for large |x|.
    x = fminf(10.0f, fmaxf(-10.0f, x));
    float e = __expf(-2.0f * x);
    return __fdividef(1.0f - e, 1.0f + e);
}

// ---------------------------------------------------------------------------
// Kernel A: xg0[t,b,g] = x[t,b,:] . w_ih0[g,:] + b_ih[0,g]   (memory-bound)
// ---------------------------------------------------------------------------
__global__ void __launch_bounds__(256) proj0_kernel(
    const float* __restrict__ x, const float* __restrict__ w_ih0,
    const float* __restrict__ b_ih)
{
    __shared__ float ws[G3 * II];
    __shared__ float bs[G3];
    for (int i = threadIdx.x; i < G3 * II; i += blockDim.x) ws[i] = w_ih0[i];
    if (threadIdx.x < G3) bs[threadIdx.x] = b_ih[threadIdx.x];
    __syncthreads();

    int idx = blockIdx.x * blockDim.x + threadIdx.x;  // (t*B + b)
    if (idx >= TT * BB) return;

    float xv[II];
    const float4* xp = (const float4*)(x + (size_t)idx * II);
#pragma unroll
    for (int q = 0; q < II / 4; ++q) {
        float4 v = xp[q];
        xv[q * 4 + 0] = v.x; xv[q * 4 + 1] = v.y;
        xv[q * 4 + 2] = v.z; xv[q * 4 + 3] = v.w;
    }
    float* o = g_xg0 + (size_t)idx * G3;
#pragma unroll
    for (int g = 0; g < G3; ++g) {
        float acc = bs[g];
#pragma unroll
        for (int k = 0; k < II; ++k) acc = fmaf(xv[k], ws[g * II + k], acc);
        o[g] = acc;
    }
}

// ---------------------------------------------------------------------------
// Kernel B: persistent single-block wavefront pipeline.
//   warp l = GRU layer l; lanes 0..5 = batch elements.
//   Round k: warp l processes chunk c = k - l (32 timesteps), consuming the
//   chunk layer l-1 produced in round k-1 (parity double buffer in smem).
// ---------------------------------------------------------------------------
__global__ void __launch_bounds__(256, 1) gru_pipeline_kernel(
    const float* __restrict__ hxs,  const float* __restrict__ w_ihR,
    const float* __restrict__ w_hh, const float* __restrict__ b_ih,
    const float* __restrict__ b_hh, float* __restrict__ out)
{
    __shared__ float hbuf[2][LL][CHUNK][BB][HH];   // 36864 B (slot 7 unused)
    __shared__ float xin[XG_CHUNK_FLOATS];         // layer-0 staged inputs

    const int tid  = threadIdx.x;
    const int l    = tid >> 5;   // layer
    const int lane = tid & 31;   // batch (0..5 active)

    // Per-lane weight copies (fully unrolled -> registers)
    float wi[G3][HH], wh[G3][HH];
    float bcomb[6];   // r,z combined bias (b_ih+b_hh for l>0; b_hh only for l==0)
    float bxn[HH];    // b_ih for n-gate (0 for l==0, already folded into xg0)
    float bhn[HH];    // b_hh for n-gate (must stay inside r*hn)
    float h[HH];

    if (lane < BB) {
#pragma unroll
        for (int g = 0; g < G3; ++g)
#pragma unroll
            for (int j = 0; j < HH; ++j) {
                wh[g][j] = w_hh[l * G3 * HH + g * HH + j];
                wi[g][j] = (l > 0) ? w_ihR[(l - 1) * G3 * HH + g * HH + j] : 0.0f;
            }
#pragma unroll
        for (int g = 0; g < 6; ++g)
            bcomb[g] = b_hh[l * G3 + g] + ((l > 0) ? b_ih[l * G3 + g] : 0.0f);
#pragma unroll
        for (int j = 0; j < HH; ++j) {
            bxn[j] = (l > 0) ? b_ih[l * G3 + 6 + j] : 0.0f;
            bhn[j] = b_hh[l * G3 + 6 + j];
            h[j]   = hxs[l * BB * HH + lane * HH + j];
        }
    }

    // Warp 0: register prefetch buffer for layer-0 xg chunks.
    float preg[PREG_N];
    if (l == 0) {
#pragma unroll
        for (int q = 0; q < PREG_N; ++q)
            preg[q] = g_xg0[lane + 32 * q];   // chunk 0
    }

    const int NR = NCH + LL - 1;
    for (int k = 0; k < NR; ++k) {
        const int c  = k - l;
        const int wp = k & 1;
        const int rp = wp ^ 1;

        // Warp 0: dump prefetched chunk c to smem, start prefetch of c+1.
        if (l == 0 && (unsigned)c < (unsigned)NCH) {
#pragma unroll
            for (int q = 0; q < PREG_N; ++q)
                xin[lane + 32 * q] = preg[q];
            __syncwarp();
            const int cn = c + 1;
            if (cn < NCH) {
                const float* src = g_xg0 + (size_t)cn * XG_CHUNK_FLOATS;
#pragma unroll
                for (int q = 0; q < PREG_N; ++q)
                    preg[q] = src[lane + 32 * q];
            }
        }

        if (lane < BB && (unsigned)c < (unsigned)NCH) {
#pragma unroll 4
            for (int s = 0; s < CHUNK; ++s) {
                // ---- input gate pre-activations (h-independent) ----
                float xa[G3];
                if (l == 0) {
                    const float* xp = &xin[s * BB * G3 + lane * G3];
#pragma unroll
                    for (int g = 0; g < G3; ++g) xa[g] = xp[g];
#pragma unroll
                    for (int g = 0; g < 6; ++g) xa[g] += bcomb[g];  // + b_hh(r,z)
                } else {
                    const float* ip = &hbuf[rp][l - 1][s][lane][0];
                    float i0 = ip[0], i1 = ip[1], i2 = ip[2];
#pragma unroll
                    for (int g = 0; g < 6; ++g)
                        xa[g] = fmaf(i2, wi[g][2],
                                fmaf(i1, wi[g][1],
                                fmaf(i0, wi[g][0], bcomb[g])));
#pragma unroll
                    for (int j = 0; j < HH; ++j)
                        xa[6 + j] = fmaf(i2, wi[6 + j][2],
                                    fmaf(i1, wi[6 + j][1],
                                    fmaf(i0, wi[6 + j][0], bxn[j])));
                }

                // ---- recurrent pre-activations ----
                float pr[HH], pz[HH], hn[HH];
#pragma unroll
                for (int j = 0; j < HH; ++j) {
                    pr[j] = fmaf(h[2], wh[j][2],
                            fmaf(h[1], wh[j][1],
                            fmaf(h[0], wh[j][0], xa[j])));
                    pz[j] = fmaf(h[2], wh[3 + j][2],
                            fmaf(h[1], wh[3 + j][1],
                            fmaf(h[0], wh[3 + j][0], xa[3 + j])));
                    hn[j] = fmaf(h[2], wh[6 + j][2],
                            fmaf(h[1], wh[6 + j][1],
                            fmaf(h[0], wh[6 + j][0], bhn[j])));
                }

                // ---- gates + state update (torch GRU rule) ----
                float hnew[HH];
#pragma unroll
                for (int j = 0; j < HH; ++j) {
                    float r = sigf(pr[j]);
                    float z = sigf(pz[j]);
                    float n = tanhf_fast(fmaf(r, hn[j], xa[6 + j]));
                    hnew[j] = fmaf(z, h[j] - n, n);   // (1-z)n + z h
                }
                h[0] = hnew[0]; h[1] = hnew[1]; h[2] = hnew[2];

                if (l < LL - 1) {
                    float* op = &hbuf[wp][l][s][lane][0];
                    op[0] = h[0]; op[1] = h[1]; op[2] = h[2];
                } else {
                    float* og = out + (size_t)(c * CHUNK + s) * BB * HH + lane * HH;
                    og[0] = h[0]; og[1] = h[1]; og[2] = h[2];
                }
            }
        }

        __syncthreads();

        // Final hidden state of this layer after its last chunk.
        if (lane < BB && c == NCH - 1) {
            float* fo = out + (size_t)TT * BB * HH + l * BB * HH + lane * HH;
            fo[0] = h[0]; fo[1] = h[1]; fo[2] = h[2];
        }
    }
}

// ---------------------------------------------------------------------------
// Launch: inputs in metadata order: x, hxs, w_ih0, w_ihR, w_hh, b_ih, b_hh.
// Output: out (T,B,H) followed by finals (L,B,H).
// ---------------------------------------------------------------------------
extern "C" void kernel_launch(void* const* d_in, const int* in_sizes, int n_in,
                              void* d_out, int out_size) {
    const float* x     = (const float*)d_in[0];
    const float* hxs   = (const float*)d_in[1];
    const float* w_ih0 = (const float*)d_in[2];
    const float* w_ihR = (const float*)d_in[3];
    const float* w_hh  = (const float*)d_in[4];
    const float* b_ih  = (const float*)d_in[5];
    const float* b_hh  = (const float*)d_in[6];
    float* out = (float*)d_out;

    const int nrows = TT * BB;
    proj0_kernel<<<(nrows + 255) / 256, 256>>>(x, w_ih0, b_ih);
    gru_pipeline_kernel<<<1, 256>>>(hxs, w_ihR, w_hh, b_ih, b_hh, out);
}

// round 2
// speedup vs baseline: 1.7959x; 1.7959x over previous
#include <cuda_runtime.h>
#include <cstdint>

// Problem constants
#define TT 131072
#define BB 6
#define II 32
#define HH 3
#define LL 8
#define G3 9                      // 3*H gate rows
#define BH (BB * HH)              // 18
#define CHUNK 32
#define NCH (TT / CHUNK)          // 4096 chunks
#define XGF (CHUNK * BB * G3)     // 1728 floats per layer-0 input chunk
#define PREG_N (XGF / 32)         // 54 per lane
#define L2E  1.4426950408889634f  // log2(e)
#define L2E2 2.8853900817779268f  // 2*log2(e)

// Scratch for layer-0 input projections: (T, B, 9)
__device__ float g_xg0[(size_t)TT * BB * G3];

__device__ __forceinline__ float frcp(float x) {
    float r; asm("rcp.approx.f32 %0, %1;" : "=f"(r) : "f"(x)); return r;
}
__device__ __forceinline__ float fex2(float x) {
    float r; asm("ex2.approx.f32 %0, %1;" : "=f"(r) : "f"(x)); return r;
}

// ---------------------------------------------------------------------------
// Kernel A: xg0[t,b,g] = x[t,b,:] . w_ih0[g,:] + b_ih[0,g]   (memory-bound)
// ---------------------------------------------------------------------------
__global__ void __launch_bounds__(256) proj0_kernel(
    const float* __restrict__ x, const float* __restrict__ w_ih0,
    const float* __restrict__ b_ih)
{
    __shared__ float ws[G3 * II];
    __shared__ float bs[G3];
    for (int i = threadIdx.x; i < G3 * II; i += blockDim.x) ws[i] = w_ih0[i];
    if (threadIdx.x < G3) bs[threadIdx.x] = b_ih[threadIdx.x];
    __syncthreads();

    int idx = blockIdx.x * blockDim.x + threadIdx.x;  // (t*B + b)
    if (idx >= TT * BB) return;

    float xv[II];
    const float4* xp = (const float4*)(x + (size_t)idx * II);
#pragma unroll
    for (int q = 0; q < II / 4; ++q) {
        float4 v = xp[q];
        xv[q * 4 + 0] = v.x; xv[q * 4 + 1] = v.y;
        xv[q * 4 + 2] = v.z; xv[q * 4 + 3] = v.w;
    }
    float* o = g_xg0 + (size_t)idx * G3;
#pragma unroll
    for (int g = 0; g < G3; ++g) {
        float acc = bs[g];
#pragma unroll
        for (int k = 0; k < II; ++k) acc = fmaf(xv[k], ws[g * II + k], acc);
        o[g] = acc;
    }
}

// One GRU cell step for this lane's (batch bc, unit jc).
// pr0/pz0 carry the input projection + combined r/z biases; xn_ carries the
// input n-projection (+ b_ih n); Bhn is the b_hh n-bias (stays inside r*hn).
#define GRU_STEP()                                                          \
    {                                                                       \
        float hA = __shfl_sync(0xffffffffu, h, srcA);                       \
        float hB = __shfl_sync(0xffffffffu, h, srcB);                       \
        float pr = fmaf(hB, whr2, fmaf(hA, whr1, fmaf(h, whr0, pr0)));      \
        float pz = fmaf(hB, whz2, fmaf(hA, whz1, fmaf(h, whz0, pz0)));      \
        float hn = fmaf(hB, whn2, fmaf(hA, whn1, fmaf(h, whn0, Bhn)));      \
        float r  = frcp(1.0f + fex2(pr * -L2E));                            \
        float z  = frcp(1.0f + fex2(pz * -L2E));                            \
        float a  = fmaf(r, hn, xn_);                                        \
        float nn = fmaf(frcp(1.0f + fex2(a * -L2E2)), 2.0f, -1.0f);         \
        float zh = z * h;                                                   \
        h = fmaf(1.0f - z, nn, zh);                                         \
    }

// ---------------------------------------------------------------------------
// Kernel B: persistent single-block wavefront pipeline.
//   warp l = GRU layer l.  lane = b*4 + j : batch b (0..5), hidden unit j (0..2).
//   Round k: warp l processes chunk c = k - l, consuming the chunk layer l-1
//   produced in round k-1 (parity double buffer in smem).
// ---------------------------------------------------------------------------
__global__ void __launch_bounds__(256, 1) gru_pipeline_kernel(
    const float* __restrict__ hxs,  const float* __restrict__ w_ihR,
    const float* __restrict__ w_hh, const float* __restrict__ b_ih,
    const float* __restrict__ b_hh, float* __restrict__ out)
{
    __shared__ float hbuf[2][LL - 1][CHUNK][BH];   // 32256 B
    __shared__ float xin[XGF];                     // 6912 B

    const int tid  = threadIdx.x;
    const int l    = tid >> 5;
    const int lane = tid & 31;
    const int b = lane >> 2, j = lane & 3;
    const int bc = (b > 5) ? 5 : b;
    const int jc = (j > 2) ? 2 : j;
    const bool valid = (j < 3) && (b < 6);
    const int j1 = (jc + 1 == 3) ? 0 : jc + 1;
    const int j2 = (j1 + 1 == 3) ? 0 : j1 + 1;
    const int srcA = (lane & ~3) + j1;
    const int srcB = (lane & ~3) + j2;
    const int sidx = bc * 3 + jc;                  // element index in an 18-vector

    // --- per-lane weights: recurrent rows (r,z,n of unit jc), columns
    // permuted to (self=jc, j1, j2) to match shfl arrival order ---
    const float* W = w_hh + l * G3 * HH;
    const int rr = jc, rz = 3 + jc, rn = 6 + jc;
    float whr0 = W[rr*3+jc], whr1 = W[rr*3+j1], whr2 = W[rr*3+j2];
    float whz0 = W[rz*3+jc], whz1 = W[rz*3+j1], whz2 = W[rz*3+j2];
    float whn0 = W[rn*3+jc], whn1 = W[rn*3+j1], whn2 = W[rn*3+j2];

    // input weights (natural column order; only used for l>0)
    float wir0 = 0, wir1 = 0, wir2 = 0, wiz0 = 0, wiz1 = 0, wiz2 = 0;
    float win0 = 0, win1 = 0, win2 = 0;
    if (l > 0) {
        const float* Wi = w_ihR + (l - 1) * G3 * HH;
        wir0 = Wi[rr*3+0]; wir1 = Wi[rr*3+1]; wir2 = Wi[rr*3+2];
        wiz0 = Wi[rz*3+0]; wiz1 = Wi[rz*3+1]; wiz2 = Wi[rz*3+2];
        win0 = Wi[rn*3+0]; win1 = Wi[rn*3+1]; win2 = Wi[rn*3+2];
    }
    const float Br  = b_hh[l*G3 + rr] + ((l > 0) ? b_ih[l*G3 + rr] : 0.0f);
    const float Bz  = b_hh[l*G3 + rz] + ((l > 0) ? b_ih[l*G3 + rz] : 0.0f);
    const float Bxn = (l > 0) ? b_ih[l*G3 + rn] : 0.0f;
    const float Bhn = b_hh[l*G3 + rn];

    float h = hxs[l * BH + sidx];

    // Warp 0: register prefetch buffer for layer-0 xg chunks.
    float preg[PREG_N];
    if (l == 0) {
#pragma unroll
        for (int q = 0; q < PREG_N; ++q)
            preg[q] = g_xg0[lane + 32 * q];   // chunk 0
    }

    const int NR = NCH + LL - 1;
    for (int k = 0; k < NR; ++k) {
        const int c  = k - l;
        const int wp = k & 1;
        const int rp = wp ^ 1;
        const bool run = ((unsigned)c < (unsigned)NCH);

        if (l == 0) {
            if (run) {
                // dump prefetched chunk c, start prefetch of c+1
#pragma unroll
                for (int q = 0; q < PREG_N; ++q)
                    xin[lane + 32 * q] = preg[q];
                __syncwarp();
                if (c + 1 < NCH) {
                    const float* src = g_xg0 + (size_t)(c + 1) * XGF;
#pragma unroll
                    for (int q = 0; q < PREG_N; ++q)
                        preg[q] = src[lane + 32 * q];
                }
                const float* xp = xin + bc * 9;
                float* hb = &hbuf[wp][0][0][sidx];
#pragma unroll 4
                for (int s = 0; s < CHUNK; ++s) {
                    float pr0 = xp[jc]     + Br;     // xg0 already holds b_ih
                    float pz0 = xp[3 + jc] + Bz;
                    float xn_ = xp[6 + jc];
                    xp += BB * G3;
                    GRU_STEP();
                    if (valid) *hb = h;
                    hb += BH;
                }
            }
        } else if (run) {
            const float* ip = &hbuf[rp][l - 1][0][bc * 3];
            float* hb = (l < LL - 1) ? &hbuf[wp][l][0][sidx]
                                     : (out + (size_t)(c * CHUNK) * BH + sidx);
#pragma unroll 4
            for (int s = 0; s < CHUNK; ++s) {
                float i0 = ip[0], i1 = ip[1], i2 = ip[2];
                ip += BH;
                float pr0 = fmaf(i2, wir2, fmaf(i1, wir1, fmaf(i0, wir0, Br)));
                float pz0 = fmaf(i2, wiz2, fmaf(i1, wiz1, fmaf(i0, wiz0, Bz)));
                float xn_ = fmaf(i2, win2, fmaf(i1, win1, fmaf(i0, win0, Bxn)));
                GRU_STEP();
                if (valid) *hb = h;
                hb += BH;
            }
        }

        __syncthreads();

        // Final hidden state of this layer after its last chunk: (L,B,H) tail.
        if (run && c == NCH - 1 && valid) {
            out[(size_t)TT * BH + l * BH + sidx] = h;
        }
    }
}

// ---------------------------------------------------------------------------
// Launch: inputs in metadata order: x, hxs, w_ih0, w_ihR, w_hh, b_ih, b_hh.
// Output: out (T,B,H) followed by finals (L,B,H).
// ---------------------------------------------------------------------------
extern "C" void kernel_launch(void* const* d_in, const int* in_sizes, int n_in,
                              void* d_out, int out_size) {
    const float* x     = (const float*)d_in[0];
    const float* hxs   = (const float*)d_in[1];
    const float* w_ih0 = (const float*)d_in[2];
    const float* w_ihR = (const float*)d_in[3];
    const float* w_hh  = (const float*)d_in[4];
    const float* b_ih  = (const float*)d_in[5];
    const float* b_hh  = (const float*)d_in[6];
    float* out = (float*)d_out;

    const int nrows = TT * BB;
    proj0_kernel<<<(nrows + 255) / 256, 256>>>(x, w_ih0, b_ih);
    gru_pipeline_kernel<<<1, 256>>>(hxs, w_ihR, w_hh, b_ih, b_hh, out);
}

// round 3
// speedup vs baseline: 3.2890x; 1.8314x over previous
#include <cuda_runtime.h>
#include <cstdint>

// Problem constants
#define TT 131072
#define BB 6
#define II 32
#define HH 3
#define LL 8
#define G3 9                      // 3*H gate rows
#define BH (BB * HH)              // 18
#define CHUNK 32
#define NCH (TT / CHUNK)          // 4096 chunks
#define XGF (CHUNK * BB * G3)     // 1728 floats per layer-0 input chunk
#define PREG_N (XGF / 32)         // 54 per lane

// Scratch for layer-0 input projections: (T, B, 9)
__device__ float g_xg0[(size_t)TT * BB * G3];

__device__ __forceinline__ float ftanh(float x) {
    float r; asm("tanh.approx.f32 %0, %1;" : "=f"(r) : "f"(x)); return r;
}

// ---------------------------------------------------------------------------
// Kernel A: xg0[t,b,g] = x[t,b,:] . w_ih0[g,:] + b_ih[0,g]   (memory-bound)
// ---------------------------------------------------------------------------
__global__ void __launch_bounds__(256) proj0_kernel(
    const float* __restrict__ x, const float* __restrict__ w_ih0,
    const float* __restrict__ b_ih)
{
    __shared__ float ws[G3 * II];
    __shared__ float bs[G3];
    for (int i = threadIdx.x; i < G3 * II; i += blockDim.x) ws[i] = w_ih0[i];
    if (threadIdx.x < G3) bs[threadIdx.x] = b_ih[threadIdx.x];
    __syncthreads();

    int idx = blockIdx.x * blockDim.x + threadIdx.x;  // (t*B + b)
    if (idx >= TT * BB) return;

    float xv[II];
    const float4* xp = (const float4*)(x + (size_t)idx * II);
#pragma unroll
    for (int q = 0; q < II / 4; ++q) {
        float4 v = xp[q];
        xv[q * 4 + 0] = v.x; xv[q * 4 + 1] = v.y;
        xv[q * 4 + 2] = v.z; xv[q * 4 + 3] = v.w;
    }
    float* o = g_xg0 + (size_t)idx * G3;
#pragma unroll
    for (int g = 0; g < G3; ++g) {
        float acc = bs[g];
#pragma unroll
        for (int k = 0; k < II; ++k) acc = fmaf(xv[k], ws[g * II + k], acc);
        o[g] = acc;
    }
}

// One GRU cell step for this lane's (batch bc, unit jc).
//   sigma(x) = 0.5*tanh(0.5x) + 0.5  (exact identity; tanh via MUFU.TANH)
//   r*hn + xn = t_r*(0.5 hn) + (0.5 hn + xn)   -- folds sigma into one fma
//   h' = (1-z)*n + z*h, with z = 0.5 t_z + 0.5, 1-z = -0.5 t_z + 0.5
#define GRU_STEP()                                                          \
    {                                                                       \
        float hA = __shfl_sync(0xffffffffu, h, srcA);                       \
        float hB = __shfl_sync(0xffffffffu, h, srcB);                       \
        float pr = fmaf(hB, whr2, fmaf(hA, whr1, fmaf(h, whr0, pr0)));      \
        float pz = fmaf(hB, whz2, fmaf(hA, whz1, fmaf(h, whz0, pz0)));      \
        float hn = fmaf(hB, whn2, fmaf(hA, whn1, fmaf(h, whn0, Bhn)));      \
        float tr = ftanh(0.5f * pr);                                        \
        float tz = ftanh(0.5f * pz);                                        \
        float hnh = 0.5f * hn;                                              \
        float cc  = fmaf(0.5f, hn, xn_);                                    \
        float a   = fmaf(tr, hnh, cc);                                      \
        float nn  = ftanh(a);                                               \
        float z   = fmaf(0.5f, tz, 0.5f);                                   \
        float omz = fmaf(-0.5f, tz, 0.5f);                                  \
        float zh  = z * h;                                                  \
        h = fmaf(omz, nn, zh);                                              \
    }

// ---------------------------------------------------------------------------
// Kernel B: persistent single-block wavefront pipeline.
//   warp l = GRU layer l.  lane = b*4 + j : batch b (0..5), hidden unit j (0..2).
//   Round k: warp l processes chunk c = k - l, consuming the chunk layer l-1
//   produced in round k-1 (parity double buffer in smem).
// ---------------------------------------------------------------------------
__global__ void __launch_bounds__(256, 1) gru_pipeline_kernel(
    const float* __restrict__ hxs,  const float* __restrict__ w_ihR,
    const float* __restrict__ w_hh, const float* __restrict__ b_ih,
    const float* __restrict__ b_hh, float* __restrict__ out)
{
    __shared__ float hbuf[2][LL - 1][CHUNK][BH];   // 32256 B
    __shared__ float xin[XGF];                     // 6912 B

    const int tid  = threadIdx.x;
    const int l    = tid >> 5;
    const int lane = tid & 31;
    const int b = lane >> 2, j = lane & 3;
    const int bc = (b > 5) ? 5 : b;
    const int jc = (j > 2) ? 2 : j;
    const bool valid = (j < 3) && (b < 6);
    const int j1 = (jc + 1 == 3) ? 0 : jc + 1;
    const int j2 = (j1 + 1 == 3) ? 0 : j1 + 1;
    const int srcA = (lane & ~3) + j1;
    const int srcB = (lane & ~3) + j2;
    const int sidx = bc * 3 + jc;                  // element index in an 18-vector

    // --- per-lane weights: recurrent rows (r,z,n of unit jc), columns
    // permuted to (self=jc, j1, j2) to match shfl arrival order ---
    const float* W = w_hh + l * G3 * HH;
    const int rr = jc, rz = 3 + jc, rn = 6 + jc;
    float whr0 = W[rr*3+jc], whr1 = W[rr*3+j1], whr2 = W[rr*3+j2];
    float whz0 = W[rz*3+jc], whz1 = W[rz*3+j1], whz2 = W[rz*3+j2];
    float whn0 = W[rn*3+jc], whn1 = W[rn*3+j1], whn2 = W[rn*3+j2];

    // input weights (natural column order; only used for l>0)
    float wir0 = 0, wir1 = 0, wir2 = 0, wiz0 = 0, wiz1 = 0, wiz2 = 0;
    float win0 = 0, win1 = 0, win2 = 0;
    if (l > 0) {
        const float* Wi = w_ihR + (l - 1) * G3 * HH;
        wir0 = Wi[rr*3+0]; wir1 = Wi[rr*3+1]; wir2 = Wi[rr*3+2];
        wiz0 = Wi[rz*3+0]; wiz1 = Wi[rz*3+1]; wiz2 = Wi[rz*3+2];
        win0 = Wi[rn*3+0]; win1 = Wi[rn*3+1]; win2 = Wi[rn*3+2];
    }
    const float Br  = b_hh[l*G3 + rr] + ((l > 0) ? b_ih[l*G3 + rr] : 0.0f);
    const float Bz  = b_hh[l*G3 + rz] + ((l > 0) ? b_ih[l*G3 + rz] : 0.0f);
    const float Bxn = (l > 0) ? b_ih[l*G3 + rn] : 0.0f;
    const float Bhn = b_hh[l*G3 + rn];

    float h = hxs[l * BH + sidx];

    // Warp 0: register prefetch buffer for layer-0 xg chunks.
    float preg[PREG_N];
    if (l == 0) {
#pragma unroll
        for (int q = 0; q < PREG_N; ++q)
            preg[q] = g_xg0[lane + 32 * q];   // chunk 0
    }

    const int NR = NCH + LL - 1;
    for (int k = 0; k < NR; ++k) {
        const int c  = k - l;
        const int wp = k & 1;
        const int rp = wp ^ 1;
        const bool run = ((unsigned)c < (unsigned)NCH);

        if (l == 0) {
            if (run) {
                // dump prefetched chunk c, start prefetch of c+1
#pragma unroll
                for (int q = 0; q < PREG_N; ++q)
                    xin[lane + 32 * q] = preg[q];
                __syncwarp();
                if (c + 1 < NCH) {
                    const float* src = g_xg0 + (size_t)(c + 1) * XGF;
#pragma unroll
                    for (int q = 0; q < PREG_N; ++q)
                        preg[q] = src[lane + 32 * q];
                }
                const float* xp = xin + bc * 9;
                float* hb = &hbuf[wp][0][0][sidx];
#pragma unroll 4
                for (int s = 0; s < CHUNK; ++s) {
                    float pr0 = xp[jc]     + Br;     // xg0 already holds b_ih
                    float pz0 = xp[3 + jc] + Bz;
                    float xn_ = xp[6 + jc];
                    xp += BB * G3;
                    GRU_STEP();
                    if (valid) *hb = h;
                    hb += BH;
                }
            }
        } else if (run) {
            const float* ip = &hbuf[rp][l - 1][0][bc * 3];
            float* hb = (l < LL - 1) ? &hbuf[wp][l][0][sidx]
                                     : (out + (size_t)(c * CHUNK) * BH + sidx);
#pragma unroll 4
            for (int s = 0; s < CHUNK; ++s) {
                float i0 = ip[0], i1 = ip[1], i2 = ip[2];
                ip += BH;
                float pr0 = fmaf(i2, wir2, fmaf(i1, wir1, fmaf(i0, wir0, Br)));
                float pz0 = fmaf(i2, wiz2, fmaf(i1, wiz1, fmaf(i0, wiz0, Bz)));
                float xn_ = fmaf(i2, win2, fmaf(i1, win1, fmaf(i0, win0, Bxn)));
                GRU_STEP();
                if (valid) *hb = h;
                hb += BH;
            }
        }

        __syncthreads();

        // Final hidden state of this layer after its last chunk: (L,B,H) tail.
        if (run && c == NCH - 1 && valid) {
            out[(size_t)TT * BH + l * BH + sidx] = h;
        }
    }
}

// ---------------------------------------------------------------------------
// Launch: inputs in metadata order: x, hxs, w_ih0, w_ihR, w_hh, b_ih, b_hh.
// Output: out (T,B,H) followed by finals (L,B,H).
// ---------------------------------------------------------------------------
extern "C" void kernel_launch(void* const* d_in, const int* in_sizes, int n_in,
                              void* d_out, int out_size) {
    const float* x     = (const float*)d_in[0];
    const float* hxs   = (const float*)d_in[1];
    const float* w_ih0 = (const float*)d_in[2];
    const float* w_ihR = (const float*)d_in[3];
    const float* w_hh  = (const float*)d_in[4];
    const float* b_ih  = (const float*)d_in[5];
    const float* b_hh  = (const float*)d_in[6];
    float* out = (float*)d_out;

    const int nrows = TT * BB;
    proj0_kernel<<<(nrows + 255) / 256, 256>>>(x, w_ih0, b_ih);
    gru_pipeline_kernel<<<1, 256>>>(hxs, w_ihR, w_hh, b_ih, b_hh, out);
}